// round 8
// baseline (speedup 1.0000x reference)
#include <cuda_runtime.h>
#include <math.h>
#include <stdint.h>

#define CCH    64
#define HWP    3136
#define MTOT   401408
#define CPI    49
#define NPAIR  3136          // 128-col chunks
#define GRIDG  296
#define GRIDA  148
#define PIT    136           // x-tile pitch (mod 32 = 8 -> conflict-free frags)
#define PN     68            // ns matrix pitch
#define NS_TF  7
#define NS_FP  2

typedef unsigned long long u64;

__device__ float d_gpart[GRIDG * 4096];
__device__ float d_spart[GRIDG * 64];
__device__ float d_qpart[GRIDG * 64];
__device__ float d_gram[4096];
__device__ float d_sums[64];
__device__ float d_sumsq[64];
__device__ float d_wm[4096];
__device__ float d_off[64];

// ---- helpers ---------------------------------------------------------------
__device__ __forceinline__ uint32_t fu(float x) { return __float_as_uint(x); }
__device__ __forceinline__ uint32_t tf32r(float x) {
    uint32_t r; asm("cvt.rna.tf32.f32 %0, %1;" : "=r"(r) : "f"(x)); return r;
}
__device__ __forceinline__ void mma8(float c[4], uint32_t a0, uint32_t a1,
                                     uint32_t a2, uint32_t a3,
                                     uint32_t b0, uint32_t b1) {
    asm("mma.sync.aligned.m16n8k8.row.col.f32.tf32.tf32.f32 "
        "{%0,%1,%2,%3}, {%4,%5,%6,%7}, {%8,%9}, {%0,%1,%2,%3};"
        : "+f"(c[0]), "+f"(c[1]), "+f"(c[2]), "+f"(c[3])
        : "r"(a0), "r"(a1), "r"(a2), "r"(a3), "r"(b0), "r"(b1));
}
__device__ __forceinline__ void fma2(u64 &acc, u64 a, u64 b) {
    asm("fma.rn.f32x2 %0, %1, %2, %0;" : "+l"(acc) : "l"(a), "l"(b));
}
__device__ __forceinline__ u64 dup2(float x) {
    u64 r; asm("mov.b64 %0, {%1, %1};" : "=l"(r) : "r"(__float_as_uint(x))); return r;
}
__device__ __forceinline__ float2 unpk(u64 v) {
    float2 f; asm("mov.b64 {%0, %1}, %2;" : "=f"(f.x), "=f"(f.y) : "l"(v)); return f;
}
__device__ __forceinline__ void cpa16(uint32_t dst, const float* src) {
    asm volatile("cp.async.ca.shared.global [%0], [%1], 16;" :: "r"(dst), "l"(src));
}
__device__ __forceinline__ void cp_commit() { asm volatile("cp.async.commit_group;"); }
__device__ __forceinline__ void cp_wait1()  { asm volatile("cp.async.wait_group 1;" ::: "memory"); }
__device__ __forceinline__ void cp_wait0()  { asm volatile("cp.async.wait_group 0;" ::: "memory"); }

// ---------------------------------------------------------------------------
// Kernel 1: Gram via tf32 mma over 128-col chunks + exact fp32 sums/sumsq.
// ---------------------------------------------------------------------------
__global__ __launch_bounds__(256, 2) void gram_kernel(const float* __restrict__ X) {
    __shared__ __align__(16) float xsh[2][64 * PIT];
    int tid = threadIdx.x, lane = tid & 31, w = tid >> 5;
    int g = lane >> 2, t = lane & 3;
    int mb = (w & 3) * 16, nb = (w >> 2) * 32;

    uint32_t sb[2];
    sb[0] = (uint32_t)__cvta_generic_to_shared(&xsh[0][0]);
    sb[1] = (uint32_t)__cvta_generic_to_shared(&xsh[1][0]);

    float acc[4][4];
#pragma unroll
    for (int j = 0; j < 4; j++)
#pragma unroll
        for (int e = 0; e < 4; e++) acc[j][e] = 0.f;
    float csum = 0.f, cq = 0.f;
    int sc = tid >> 2, sp = (tid & 3) * 8;   // channel-sum assignment

    {   // preload chunk 0
        int ch = blockIdx.x;
        int c0 = 2 * ch, c1 = c0 + 1;
        int b0 = c0 / CPI, b1 = c1 / CPI;
        const float* bp0 = X + b0 * CCH * HWP + (c0 - b0 * CPI) * 64;
        const float* bp1 = X + b1 * CCH * HWP + (c1 - b1 * CPI) * 64;
#pragma unroll
        for (int i = 0; i < 8; i++) {
            int f = tid + 256 * i;
            int c = f >> 5, r = f & 31;
            const float* src = ((r >> 4) ? bp1 : bp0) + c * HWP + (r & 15) * 4;
            cpa16(sb[0] + (c * PIT + r * 4) * 4, src);
        }
        cp_commit();
    }

    int buf = 0;
    for (int ch = blockIdx.x; ch < NPAIR; ch += GRIDG) {
        int cn = ch + GRIDG;
        if (cn < NPAIR) {
            int c0 = 2 * cn, c1 = c0 + 1;
            int b0 = c0 / CPI, b1 = c1 / CPI;
            const float* bp0 = X + b0 * CCH * HWP + (c0 - b0 * CPI) * 64;
            const float* bp1 = X + b1 * CCH * HWP + (c1 - b1 * CPI) * 64;
#pragma unroll
            for (int i = 0; i < 8; i++) {
                int f = tid + 256 * i;
                int c = f >> 5, r = f & 31;
                const float* src = ((r >> 4) ? bp1 : bp0) + c * HWP + (r & 15) * 4;
                cpa16(sb[buf ^ 1] + (c * PIT + r * 4) * 4, src);
            }
            cp_commit();
            cp_wait1();
        } else {
            cp_wait0();
        }
        __syncthreads();

        const float* xb = &xsh[buf][0];

        {   // exact sums / sumsq: all 256 threads, 8 float4 each
            const float4* r = (const float4*)&xb[sc * PIT] + sp;
            float s = 0.f, q2 = 0.f;
#pragma unroll
            for (int q = 0; q < 8; q++) {
                float4 v = r[q];
                s  += (v.x + v.y) + (v.z + v.w);
                q2 += v.x * v.x + v.y * v.y + v.z * v.z + v.w * v.w;
            }
            csum += s; cq += q2;
        }

#pragma unroll
        for (int kg = 0; kg < 4; kg++) {
            int kb = kg * 32;
            float4 Al  = *(const float4*)&xb[(mb + g)     * PIT + kb + 4 * t];
            float4 Ah  = *(const float4*)&xb[(mb + g)     * PIT + kb + 16 + 4 * t];
            float4 A2l = *(const float4*)&xb[(mb + g + 8) * PIT + kb + 4 * t];
            float4 A2h = *(const float4*)&xb[(mb + g + 8) * PIT + kb + 16 + 4 * t];
#pragma unroll
            for (int j = 0; j < 4; j++) {
                float4 Bl = *(const float4*)&xb[(nb + 8 * j + g) * PIT + kb + 4 * t];
                float4 Bh = *(const float4*)&xb[(nb + 8 * j + g) * PIT + kb + 16 + 4 * t];
                mma8(acc[j], fu(Al.x), fu(A2l.x), fu(Ah.x), fu(A2h.x), fu(Bl.x), fu(Bh.x));
                mma8(acc[j], fu(Al.y), fu(A2l.y), fu(Ah.y), fu(A2h.y), fu(Bl.y), fu(Bh.y));
                mma8(acc[j], fu(Al.z), fu(A2l.z), fu(Ah.z), fu(A2h.z), fu(Bl.z), fu(Bh.z));
                mma8(acc[j], fu(Al.w), fu(A2l.w), fu(Ah.w), fu(A2h.w), fu(Bl.w), fu(Bh.w));
            }
        }
        __syncthreads();
        buf ^= 1;
    }

    float* gp = &d_gpart[blockIdx.x * 4096];
#pragma unroll
    for (int j = 0; j < 4; j++) {
        int col = nb + 8 * j + 2 * t;
        gp[(mb + g)     * 64 + col]     = acc[j][0];
        gp[(mb + g)     * 64 + col + 1] = acc[j][1];
        gp[(mb + g + 8) * 64 + col]     = acc[j][2];
        gp[(mb + g + 8) * 64 + col + 1] = acc[j][3];
    }
    // reduce 4 partials per channel within the warp
    csum += __shfl_xor_sync(0xffffffffu, csum, 1);
    csum += __shfl_xor_sync(0xffffffffu, csum, 2);
    cq   += __shfl_xor_sync(0xffffffffu, cq, 1);
    cq   += __shfl_xor_sync(0xffffffffu, cq, 2);
    if ((tid & 3) == 0) {
        d_spart[blockIdx.x * 64 + sc] = csum;
        d_qpart[blockIdx.x * 64 + sc] = cq;
    }
}

// ---------------------------------------------------------------------------
// Kernel 1b: reduce per-CTA partials.
// ---------------------------------------------------------------------------
__global__ __launch_bounds__(128) void reduce_kernel() {
    int idx = blockIdx.x * 128 + threadIdx.x;
    if (idx < 4096) {
        float s = 0.f;
#pragma unroll 4
        for (int c = 0; c < GRIDG; c++) s += d_gpart[c * 4096 + idx];
        d_gram[idx] = s;
    } else if (idx < 4160) {
        int j = idx - 4096;
        float s = 0.f;
#pragma unroll 4
        for (int c = 0; c < GRIDG; c++) s += d_spart[c * 64 + j];
        d_sums[j] = s;
    } else if (idx < 4224) {
        int j = idx - 4160;
        float s = 0.f;
#pragma unroll 4
        for (int c = 0; c < GRIDG; c++) s += d_qpart[c * 64 + j];
        d_sumsq[j] = s;
    }
}

// ---------------------------------------------------------------------------
// Kernel 2: Sigma + Newton-Schulz, 2-stage iterations.
// stage1: T1 = P@P, T2 = P@Sigma_N (independent). stage2: P = 1.5P - 0.5 T1@T2
// ---------------------------------------------------------------------------
__device__ __forceinline__ void mm_tf(const float* __restrict__ A,
                                      const float* __restrict__ Bm,
                                      int g, int t, int mb, int nb,
                                      float acc[4][4]) {
#pragma unroll
    for (int j = 0; j < 4; j++)
#pragma unroll
        for (int e = 0; e < 4; e++) acc[j][e] = 0.f;
#pragma unroll
    for (int ks = 0; ks < 8; ks++) {
        uint32_t a0 = fu(A[(mb + g)     * PN + 8 * ks + t]);
        uint32_t a1 = fu(A[(mb + g + 8) * PN + 8 * ks + t]);
        uint32_t a2 = fu(A[(mb + g)     * PN + 8 * ks + t + 4]);
        uint32_t a3 = fu(A[(mb + g + 8) * PN + 8 * ks + t + 4]);
#pragma unroll
        for (int j = 0; j < 4; j++) {
            uint32_t b0 = fu(Bm[(8 * ks + t)     * PN + nb + 8 * j + g]);
            uint32_t b1 = fu(Bm[(8 * ks + t + 4) * PN + nb + 8 * j + g]);
            mma8(acc[j], a0, a1, a2, a3, b0, b1);
        }
    }
}

__device__ __forceinline__ void st_tf(float* __restrict__ D, int g, int t,
                                      int mb, int nb, const float acc[4][4]) {
#pragma unroll
    for (int j = 0; j < 4; j++) {
        int c0 = nb + 8 * j + 2 * t;
        *(float2*)&D[(mb + g)     * PN + c0] = make_float2(acc[j][0], acc[j][1]);
        *(float2*)&D[(mb + g + 8) * PN + c0] = make_float2(acc[j][2], acc[j][3]);
    }
}

__device__ __forceinline__ void mm_sym(const float* __restrict__ A,
                                       const float* __restrict__ Bm,
                                       int ib, int jb, u64 acc[4][2]) {
#pragma unroll
    for (int ii = 0; ii < 4; ii++) { acc[ii][0] = 0ull; acc[ii][1] = 0ull; }
#pragma unroll 8
    for (int k = 0; k < 64; k++) {
        float4 a = *(const float4*)&A[k * PN + ib];
        ulonglong2 bv = *(const ulonglong2*)&Bm[k * PN + jb];
        u64 d0 = dup2(a.x), d1 = dup2(a.y), d2 = dup2(a.z), d3 = dup2(a.w);
        fma2(acc[0][0], d0, bv.x); fma2(acc[0][1], d0, bv.y);
        fma2(acc[1][0], d1, bv.x); fma2(acc[1][1], d1, bv.y);
        fma2(acc[2][0], d2, bv.x); fma2(acc[2][1], d2, bv.y);
        fma2(acc[3][0], d3, bv.x); fma2(acc[3][1], d3, bv.y);
    }
}

__device__ __forceinline__ void store4(float* __restrict__ D, int ib, int jb,
                                       u64 acc[4][2]) {
#pragma unroll
    for (int ii = 0; ii < 4; ii++) {
        float2 l0 = unpk(acc[ii][0]);
        float2 l1 = unpk(acc[ii][1]);
        *(float4*)&D[(ib + ii) * PN + jb] = make_float4(l0.x, l0.y, l1.x, l1.y);
    }
}

__global__ __launch_bounds__(256) void ns_kernel(const float* __restrict__ beta) {
    __shared__ __align__(16) float B0[64 * PN];  // P
    __shared__ __align__(16) float B1[64 * PN];  // Sigma_N
    __shared__ __align__(16) float B2[64 * PN];  // T1
    __shared__ __align__(16) float B3[64 * PN];  // T2
    int tid = threadIdx.x, lane = tid & 31, w = tid >> 5;
    int g = lane >> 2, t = lane & 3;
    int mb = (w & 3) * 16, nb = (w >> 2) * 32;
    int ib = (tid >> 4) * 4, jb = (tid & 15) * 4;
    const float inv_m = 1.f / (float)MTOT;

    for (int idx = tid; idx < 4096; idx += 256) {
        int i = idx >> 6, j = idx & 63;
        float mi = d_sums[i] * inv_m, mj = d_sums[j] * inv_m;
        float s;
        if (i == j) s = d_sumsq[i] * inv_m - mi * mi + 1e-5f;
        else        s = (d_gram[idx] * inv_m - mi * mj) * 0.9f;
        B1[i * PN + j] = s;
    }
    __syncthreads();

    if (tid < 32) {
        float s = B1[tid * PN + tid] + B1[(tid + 32) * PN + (tid + 32)];
#pragma unroll
        for (int o = 16; o > 0; o >>= 1) s += __shfl_xor_sync(0xffffffffu, s, o);
        if (tid == 0) B2[0] = s;
    }
    __syncthreads();
    float rTr = 1.f / B2[0];
    float srt = sqrtf(rTr);
    __syncthreads();

    for (int idx = tid; idx < 4096; idx += 256) {
        int i = idx >> 6, j = idx & 63;
        float sn = B1[i * PN + j] * rTr;
        B1[i * PN + j] = sn;
        B0[i * PN + j] = (i == j ? 1.5f : 0.f) - 0.5f * sn;
    }
    __syncthreads();

    float a4[4][4], b4[4][4];
    for (int it = 0; it < NS_TF; it++) {
        // stage 1: T1 = P@P, T2 = P@Sigma_N
        mm_tf(B0, B0, g, t, mb, nb, a4);
        mm_tf(B0, B1, g, t, mb, nb, b4);
        st_tf(B2, g, t, mb, nb, a4);
        st_tf(B3, g, t, mb, nb, b4);
        __syncthreads();
        // stage 2: P = 1.5P - 0.5 * T1@T2
        mm_tf(B2, B3, g, t, mb, nb, a4);
#pragma unroll
        for (int j = 0; j < 4; j++) {
            int c0 = nb + 8 * j + 2 * t;
            float2 p0 = *(const float2*)&B0[(mb + g)     * PN + c0];
            float2 p1 = *(const float2*)&B0[(mb + g + 8) * PN + c0];
            *(float2*)&B0[(mb + g)     * PN + c0] =
                make_float2(1.5f * p0.x - 0.5f * a4[j][0], 1.5f * p0.y - 0.5f * a4[j][1]);
            *(float2*)&B0[(mb + g + 8) * PN + c0] =
                make_float2(1.5f * p1.x - 0.5f * a4[j][2], 1.5f * p1.y - 0.5f * a4[j][3]);
        }
        __syncthreads();
    }

    // exact fp32 final iterations (2-stage as well)
    u64 acc[4][2], acc2[4][2];
    for (int it = 0; it < NS_FP; it++) {
        mm_sym(B0, B0, ib, jb, acc);
        mm_sym(B0, B1, ib, jb, acc2);
        store4(B2, ib, jb, acc);
        store4(B3, ib, jb, acc2);
        __syncthreads();
        mm_sym(B2, B3, ib, jb, acc);
#pragma unroll
        for (int ii = 0; ii < 4; ii++) {
            float2 l0 = unpk(acc[ii][0]);
            float2 l1 = unpk(acc[ii][1]);
            int base = (ib + ii) * PN + jb;
            float4 p = *(const float4*)&B0[base];
            *(float4*)&B0[base] = make_float4(1.5f * p.x - 0.5f * l0.x,
                                              1.5f * p.y - 0.5f * l0.y,
                                              1.5f * p.z - 0.5f * l1.x,
                                              1.5f * p.w - 0.5f * l1.y);
        }
        __syncthreads();
    }

#pragma unroll
    for (int ii = 0; ii < 4; ii++) {
        float4 p = *(const float4*)&B0[(ib + ii) * PN + jb];
        *(float4*)&d_wm[(ib + ii) * 64 + jb] =
            make_float4(p.x * srt, p.y * srt, p.z * srt, p.w * srt);
    }
    if (tid < 64) {
        float s = 0.f;
#pragma unroll 8
        for (int j = 0; j < 64; j++) s += B0[tid * PN + j] * (d_sums[j] * inv_m);
        d_off[tid] = beta[tid] - srt * s;
    }
}

// ---------------------------------------------------------------------------
// Kernel 3: out = x + E@x + off over 128-col chunks, 512 threads, 1 CTA/SM.
// ---------------------------------------------------------------------------
__global__ __launch_bounds__(512, 1) void apply_kernel(const float* __restrict__ X,
                                                       float* __restrict__ out) {
    __shared__ __align__(16) float xsh[2][64 * PIT];
    __shared__ __align__(16) float ysh[64 * PIT];
    __shared__ float osh[64];
    int tid = threadIdx.x, lane = tid & 31, w = tid >> 5;
    int g = lane >> 2, t = lane & 3;
    int mb = (w >> 3) * 32;        // 0 or 32
    int nb = (w & 7) * 16;         // 0..112

    uint32_t sb[2];
    sb[0] = (uint32_t)__cvta_generic_to_shared(&xsh[0][0]);
    sb[1] = (uint32_t)__cvta_generic_to_shared(&xsh[1][0]);

    uint32_t ea[2][8][4];
#pragma unroll
    for (int mi = 0; mi < 2; mi++) {
        int r0 = mb + 16 * mi + g, r1 = r0 + 8;
#pragma unroll
        for (int ks = 0; ks < 8; ks++) {
            int c0 = 8 * ks + t, c1 = c0 + 4;
            ea[mi][ks][0] = tf32r(d_wm[r0 * 64 + c0] - (r0 == c0 ? 1.f : 0.f));
            ea[mi][ks][1] = tf32r(d_wm[r1 * 64 + c0] - (r1 == c0 ? 1.f : 0.f));
            ea[mi][ks][2] = tf32r(d_wm[r0 * 64 + c1] - (r0 == c1 ? 1.f : 0.f));
            ea[mi][ks][3] = tf32r(d_wm[r1 * 64 + c1] - (r1 == c1 ? 1.f : 0.f));
        }
    }
    if (tid < 64) osh[tid] = d_off[tid];

    {   // preload
        int ch = blockIdx.x;
        int c0 = 2 * ch, c1 = c0 + 1;
        int b0 = c0 / CPI, b1 = c1 / CPI;
        const float* bp0 = X + b0 * CCH * HWP + (c0 - b0 * CPI) * 64;
        const float* bp1 = X + b1 * CCH * HWP + (c1 - b1 * CPI) * 64;
#pragma unroll
        for (int i = 0; i < 4; i++) {
            int f = tid + 512 * i;
            int c = f >> 5, r = f & 31;
            const float* src = ((r >> 4) ? bp1 : bp0) + c * HWP + (r & 15) * 4;
            cpa16(sb[0] + (c * PIT + r * 4) * 4, src);
        }
        cp_commit();
    }

    int buf = 0;
    for (int ch = blockIdx.x; ch < NPAIR; ch += GRIDA) {
        int cn = ch + GRIDA;
        if (cn < NPAIR) {
            int c0 = 2 * cn, c1 = c0 + 1;
            int b0 = c0 / CPI, b1 = c1 / CPI;
            const float* bp0 = X + b0 * CCH * HWP + (c0 - b0 * CPI) * 64;
            const float* bp1 = X + b1 * CCH * HWP + (c1 - b1 * CPI) * 64;
#pragma unroll
            for (int i = 0; i < 4; i++) {
                int f = tid + 512 * i;
                int c = f >> 5, r = f & 31;
                const float* src = ((r >> 4) ? bp1 : bp0) + c * HWP + (r & 15) * 4;
                cpa16(sb[buf ^ 1] + (c * PIT + r * 4) * 4, src);
            }
            cp_commit();
            cp_wait1();
        } else {
            cp_wait0();
        }
        __syncthreads();

        const float* xb = &xsh[buf][0];
        float acc[2][2][4];
#pragma unroll
        for (int mi = 0; mi < 2; mi++)
#pragma unroll
            for (int j = 0; j < 2; j++)
#pragma unroll
                for (int e = 0; e < 4; e++) acc[mi][j][e] = 0.f;

#pragma unroll
        for (int ks = 0; ks < 8; ks++) {
            uint32_t b00 = fu(xb[(8 * ks + t)     * PIT + nb + g]);
            uint32_t b01 = fu(xb[(8 * ks + t + 4) * PIT + nb + g]);
            uint32_t b10 = fu(xb[(8 * ks + t)     * PIT + nb + 8 + g]);
            uint32_t b11 = fu(xb[(8 * ks + t + 4) * PIT + nb + 8 + g]);
#pragma unroll
            for (int mi = 0; mi < 2; mi++) {
                mma8(acc[mi][0], ea[mi][ks][0], ea[mi][ks][1],
                                 ea[mi][ks][2], ea[mi][ks][3], b00, b01);
                mma8(acc[mi][1], ea[mi][ks][0], ea[mi][ks][1],
                                 ea[mi][ks][2], ea[mi][ks][3], b10, b11);
            }
        }

#pragma unroll
        for (int mi = 0; mi < 2; mi++) {
            int r0 = mb + 16 * mi + g, r1 = r0 + 8;
#pragma unroll
            for (int j = 0; j < 2; j++) {
                int cc = nb + 8 * j + 2 * t;
                *(float2*)&ysh[r0 * PIT + cc] = make_float2(acc[mi][j][0], acc[mi][j][1]);
                *(float2*)&ysh[r1 * PIT + cc] = make_float2(acc[mi][j][2], acc[mi][j][3]);
            }
        }
        __syncthreads();

        // coalesced output: out = x + E@x + off
        int c0 = 2 * ch, c1 = c0 + 1;
        int b0 = c0 / CPI, b1 = c1 / CPI;
        float* op0 = out + b0 * CCH * HWP + (c0 - b0 * CPI) * 64;
        float* op1 = out + b1 * CCH * HWP + (c1 - b1 * CPI) * 64;
#pragma unroll
        for (int i = 0; i < 4; i++) {
            int f = tid + 512 * i;
            int c = f >> 5, r = f & 31;
            float4 xv = *(const float4*)&xb[c * PIT + r * 4];
            float4 yv = *(const float4*)&ysh[c * PIT + r * 4];
            float o = osh[c];
            float* dst = ((r >> 4) ? op1 : op0) + c * HWP + (r & 15) * 4;
            *(float4*)dst = make_float4(xv.x + yv.x + o, xv.y + yv.y + o,
                                        xv.z + yv.z + o, xv.w + yv.w + o);
        }
        __syncthreads();
        buf ^= 1;
    }
}

extern "C" void kernel_launch(void* const* d_in, const int* in_sizes, int n_in,
                              void* d_out, int out_size) {
    (void)in_sizes; (void)n_in; (void)out_size;
    const float* X    = (const float*)d_in[0];
    const float* beta = (const float*)d_in[1];
    float* out        = (float*)d_out;

    gram_kernel<<<GRIDG, 256>>>(X);
    reduce_kernel<<<33, 128>>>();
    ns_kernel<<<1, 256>>>(beta);
    apply_kernel<<<GRIDA, 512>>>(X, out);
}

// round 9
// speedup vs baseline: 1.1013x; 1.1013x over previous
#include <cuda_runtime.h>
#include <math.h>
#include <stdint.h>

#define CCH    64
#define HWP    3136
#define MTOT   401408
#define CPI    49
#define NCHUNK 6272
#define GRIDB  296
#define PG     80           // gram tile pitch
#define PA     68           // apply tile pitch
#define PN     68           // ns matrix pitch
#define NS_TF  7
#define NS_FP  2

typedef unsigned long long u64;

__device__ float d_gpart[GRIDB * 4096];
__device__ float d_spart[GRIDB * 64];
__device__ float d_qpart[GRIDB * 64];
__device__ float d_gram[4096];
__device__ float d_sums[64];
__device__ float d_sumsq[64];
__device__ float d_wm[4096];
__device__ float d_off[64];

// ---- helpers ---------------------------------------------------------------
__device__ __forceinline__ uint32_t fu(float x) { return __float_as_uint(x); }
__device__ __forceinline__ uint32_t tf32r(float x) {
    uint32_t r; asm("cvt.rna.tf32.f32 %0, %1;" : "=r"(r) : "f"(x)); return r;
}
__device__ __forceinline__ void mma8(float c[4], uint32_t a0, uint32_t a1,
                                     uint32_t a2, uint32_t a3,
                                     uint32_t b0, uint32_t b1) {
    asm("mma.sync.aligned.m16n8k8.row.col.f32.tf32.tf32.f32 "
        "{%0,%1,%2,%3}, {%4,%5,%6,%7}, {%8,%9}, {%0,%1,%2,%3};"
        : "+f"(c[0]), "+f"(c[1]), "+f"(c[2]), "+f"(c[3])
        : "r"(a0), "r"(a1), "r"(a2), "r"(a3), "r"(b0), "r"(b1));
}
__device__ __forceinline__ void fma2(u64 &acc, u64 a, u64 b) {
    asm("fma.rn.f32x2 %0, %1, %2, %0;" : "+l"(acc) : "l"(a), "l"(b));
}
__device__ __forceinline__ u64 dup2(float x) {
    u64 r; asm("mov.b64 %0, {%1, %1};" : "=l"(r) : "r"(__float_as_uint(x))); return r;
}
__device__ __forceinline__ float2 unpk(u64 v) {
    float2 f; asm("mov.b64 {%0, %1}, %2;" : "=f"(f.x), "=f"(f.y) : "l"(v)); return f;
}
__device__ __forceinline__ void cpa16(uint32_t dst, const float* src) {
    asm volatile("cp.async.ca.shared.global [%0], [%1], 16;" :: "r"(dst), "l"(src));
}
__device__ __forceinline__ void cp_commit() { asm volatile("cp.async.commit_group;"); }
__device__ __forceinline__ void cp_wait1()  { asm volatile("cp.async.wait_group 1;" ::: "memory"); }

// ---------------------------------------------------------------------------
// Kernel 1: Gram via tf32 mma, 3-buffer pipeline, ONE barrier per chunk.
// ---------------------------------------------------------------------------
__global__ __launch_bounds__(256, 2) void gram_kernel(const float* __restrict__ X) {
    __shared__ __align__(16) float xsh[3][64 * PG];   // 60 KB
    int tid = threadIdx.x, lane = tid & 31, w = tid >> 5;
    int g = lane >> 2, t = lane & 3;
    int mb = (w & 3) * 16, nb = (w >> 2) * 32;

    uint32_t sb[3];
    sb[0] = (uint32_t)__cvta_generic_to_shared(&xsh[0][0]);
    sb[1] = (uint32_t)__cvta_generic_to_shared(&xsh[1][0]);
    sb[2] = (uint32_t)__cvta_generic_to_shared(&xsh[2][0]);

    float acc[4][4];
#pragma unroll
    for (int j = 0; j < 4; j++)
#pragma unroll
        for (int e = 0; e < 4; e++) acc[j][e] = 0.f;
    float csum = 0.f, cq = 0.f;

    // preload chunks k and k+1 into slots 0,1
#pragma unroll
    for (int p = 0; p < 2; p++) {
        int ch = blockIdx.x + p * GRIDB;
        int b = ch / CPI, pc = (ch - b * CPI) * 64;
        const float* base = X + b * CCH * HWP + pc;
#pragma unroll
        for (int i = 0; i < 4; i++) {
            int f = tid + 256 * i;
            int c = f >> 4, q = f & 15;
            cpa16(sb[p] + (c * PG + q * 4) * 4, base + c * HWP + q * 4);
        }
        cp_commit();
    }

    int s = 0;
    for (int ch = blockIdx.x; ch < NCHUNK; ch += GRIDB) {
        cp_wait1();                 // slot s data complete
        __syncthreads();            // visible to all; prior epoch done

        // prefetch chunk+2 into slot (s+2)%3  (that slot's last use ended pre-barrier)
        int cn = ch + 2 * GRIDB;
        if (cn < NCHUNK) {
            int sn = s + 2; if (sn >= 3) sn -= 3;
            int b = cn / CPI, pc = (cn - b * CPI) * 64;
            const float* base = X + b * CCH * HWP + pc;
#pragma unroll
            for (int i = 0; i < 4; i++) {
                int f = tid + 256 * i;
                int c = f >> 4, q = f & 15;
                cpa16(sb[sn] + (c * PG + q * 4) * 4, base + c * HWP + q * 4);
            }
            cp_commit();
        }

        const float* xb = &xsh[s][0];

        if (tid < 64) {     // exact fp32 sums / sumsq
            const float4* r = (const float4*)&xb[tid * PG];
            float sv = 0.f, q2 = 0.f;
#pragma unroll
            for (int q = 0; q < 16; q++) {
                float4 v = r[q];
                sv += (v.x + v.y) + (v.z + v.w);
                q2 += v.x * v.x + v.y * v.y + v.z * v.z + v.w * v.w;
            }
            csum += sv; cq += q2;
        }

#pragma unroll
        for (int kg = 0; kg < 2; kg++) {
            int kb = kg * 32;
            float4 Al  = *(const float4*)&xb[(mb + g)     * PG + kb + 4 * t];
            float4 Ah  = *(const float4*)&xb[(mb + g)     * PG + kb + 16 + 4 * t];
            float4 A2l = *(const float4*)&xb[(mb + g + 8) * PG + kb + 4 * t];
            float4 A2h = *(const float4*)&xb[(mb + g + 8) * PG + kb + 16 + 4 * t];
#pragma unroll
            for (int j = 0; j < 4; j++) {
                float4 Bl = *(const float4*)&xb[(nb + 8 * j + g) * PG + kb + 4 * t];
                float4 Bh = *(const float4*)&xb[(nb + 8 * j + g) * PG + kb + 16 + 4 * t];
                mma8(acc[j], fu(Al.x), fu(A2l.x), fu(Ah.x), fu(A2h.x), fu(Bl.x), fu(Bh.x));
                mma8(acc[j], fu(Al.y), fu(A2l.y), fu(Ah.y), fu(A2h.y), fu(Bl.y), fu(Bh.y));
                mma8(acc[j], fu(Al.z), fu(A2l.z), fu(Ah.z), fu(A2h.z), fu(Bl.z), fu(Bh.z));
                mma8(acc[j], fu(Al.w), fu(A2l.w), fu(Ah.w), fu(A2h.w), fu(Bl.w), fu(Bh.w));
            }
        }
        s++; if (s >= 3) s -= 3;
    }

    float* gp = &d_gpart[blockIdx.x * 4096];
#pragma unroll
    for (int j = 0; j < 4; j++) {
        int col = nb + 8 * j + 2 * t;
        gp[(mb + g)     * 64 + col]     = acc[j][0];
        gp[(mb + g)     * 64 + col + 1] = acc[j][1];
        gp[(mb + g + 8) * 64 + col]     = acc[j][2];
        gp[(mb + g + 8) * 64 + col + 1] = acc[j][3];
    }
    if (tid < 64) {
        d_spart[blockIdx.x * 64 + tid] = csum;
        d_qpart[blockIdx.x * 64 + tid] = cq;
    }
}

// ---------------------------------------------------------------------------
// Kernel 1b: reduce per-CTA partials.
// ---------------------------------------------------------------------------
__global__ __launch_bounds__(128) void reduce_kernel() {
    int idx = blockIdx.x * 128 + threadIdx.x;
    if (idx < 4096) {
        float s = 0.f;
#pragma unroll 4
        for (int c = 0; c < GRIDB; c++) s += d_gpart[c * 4096 + idx];
        d_gram[idx] = s;
    } else if (idx < 4160) {
        int j = idx - 4096;
        float s = 0.f;
#pragma unroll 4
        for (int c = 0; c < GRIDB; c++) s += d_spart[c * 64 + j];
        d_sums[j] = s;
    } else if (idx < 4224) {
        int j = idx - 4160;
        float s = 0.f;
#pragma unroll 4
        for (int c = 0; c < GRIDB; c++) s += d_qpart[c * 64 + j];
        d_sumsq[j] = s;
    }
}

// ---------------------------------------------------------------------------
// Kernel 2: Sigma + Newton-Schulz, 2-stage iterations.
// ---------------------------------------------------------------------------
__device__ __forceinline__ void mm_tf(const float* __restrict__ A,
                                      const float* __restrict__ Bm,
                                      int g, int t, int mb, int nb,
                                      float acc[4][4]) {
#pragma unroll
    for (int j = 0; j < 4; j++)
#pragma unroll
        for (int e = 0; e < 4; e++) acc[j][e] = 0.f;
#pragma unroll
    for (int ks = 0; ks < 8; ks++) {
        uint32_t a0 = fu(A[(mb + g)     * PN + 8 * ks + t]);
        uint32_t a1 = fu(A[(mb + g + 8) * PN + 8 * ks + t]);
        uint32_t a2 = fu(A[(mb + g)     * PN + 8 * ks + t + 4]);
        uint32_t a3 = fu(A[(mb + g + 8) * PN + 8 * ks + t + 4]);
#pragma unroll
        for (int j = 0; j < 4; j++) {
            uint32_t b0 = fu(Bm[(8 * ks + t)     * PN + nb + 8 * j + g]);
            uint32_t b1 = fu(Bm[(8 * ks + t + 4) * PN + nb + 8 * j + g]);
            mma8(acc[j], a0, a1, a2, a3, b0, b1);
        }
    }
}

__device__ __forceinline__ void st_tf(float* __restrict__ D, int g, int t,
                                      int mb, int nb, const float acc[4][4]) {
#pragma unroll
    for (int j = 0; j < 4; j++) {
        int c0 = nb + 8 * j + 2 * t;
        *(float2*)&D[(mb + g)     * PN + c0] = make_float2(acc[j][0], acc[j][1]);
        *(float2*)&D[(mb + g + 8) * PN + c0] = make_float2(acc[j][2], acc[j][3]);
    }
}

__device__ __forceinline__ void mm_sym(const float* __restrict__ A,
                                       const float* __restrict__ Bm,
                                       int ib, int jb, u64 acc[4][2]) {
#pragma unroll
    for (int ii = 0; ii < 4; ii++) { acc[ii][0] = 0ull; acc[ii][1] = 0ull; }
#pragma unroll 8
    for (int k = 0; k < 64; k++) {
        float4 a = *(const float4*)&A[k * PN + ib];
        ulonglong2 bv = *(const ulonglong2*)&Bm[k * PN + jb];
        u64 d0 = dup2(a.x), d1 = dup2(a.y), d2 = dup2(a.z), d3 = dup2(a.w);
        fma2(acc[0][0], d0, bv.x); fma2(acc[0][1], d0, bv.y);
        fma2(acc[1][0], d1, bv.x); fma2(acc[1][1], d1, bv.y);
        fma2(acc[2][0], d2, bv.x); fma2(acc[2][1], d2, bv.y);
        fma2(acc[3][0], d3, bv.x); fma2(acc[3][1], d3, bv.y);
    }
}

__device__ __forceinline__ void store4(float* __restrict__ D, int ib, int jb,
                                       u64 acc[4][2]) {
#pragma unroll
    for (int ii = 0; ii < 4; ii++) {
        float2 l0 = unpk(acc[ii][0]);
        float2 l1 = unpk(acc[ii][1]);
        *(float4*)&D[(ib + ii) * PN + jb] = make_float4(l0.x, l0.y, l1.x, l1.y);
    }
}

__global__ __launch_bounds__(256) void ns_kernel(const float* __restrict__ beta) {
    __shared__ __align__(16) float B0[64 * PN];
    __shared__ __align__(16) float B1[64 * PN];
    __shared__ __align__(16) float B2[64 * PN];
    __shared__ __align__(16) float B3[64 * PN];
    int tid = threadIdx.x, lane = tid & 31, w = tid >> 5;
    int g = lane >> 2, t = lane & 3;
    int mb = (w & 3) * 16, nb = (w >> 2) * 32;
    int ib = (tid >> 4) * 4, jb = (tid & 15) * 4;
    const float inv_m = 1.f / (float)MTOT;

    for (int idx = tid; idx < 4096; idx += 256) {
        int i = idx >> 6, j = idx & 63;
        float mi = d_sums[i] * inv_m, mj = d_sums[j] * inv_m;
        float s;
        if (i == j) s = d_sumsq[i] * inv_m - mi * mi + 1e-5f;
        else        s = (d_gram[idx] * inv_m - mi * mj) * 0.9f;
        B1[i * PN + j] = s;
    }
    __syncthreads();

    if (tid < 32) {
        float s = B1[tid * PN + tid] + B1[(tid + 32) * PN + (tid + 32)];
#pragma unroll
        for (int o = 16; o > 0; o >>= 1) s += __shfl_xor_sync(0xffffffffu, s, o);
        if (tid == 0) B2[0] = s;
    }
    __syncthreads();
    float rTr = 1.f / B2[0];
    float srt = sqrtf(rTr);
    __syncthreads();

    for (int idx = tid; idx < 4096; idx += 256) {
        int i = idx >> 6, j = idx & 63;
        float sn = B1[i * PN + j] * rTr;
        B1[i * PN + j] = sn;
        B0[i * PN + j] = (i == j ? 1.5f : 0.f) - 0.5f * sn;
    }
    __syncthreads();

    float a4[4][4], b4[4][4];
    for (int it = 0; it < NS_TF; it++) {
        mm_tf(B0, B0, g, t, mb, nb, a4);     // T1 = P@P
        mm_tf(B0, B1, g, t, mb, nb, b4);     // T2 = P@Sigma_N
        st_tf(B2, g, t, mb, nb, a4);
        st_tf(B3, g, t, mb, nb, b4);
        __syncthreads();
        mm_tf(B2, B3, g, t, mb, nb, a4);     // T1@T2 = P^3 Sigma_N
#pragma unroll
        for (int j = 0; j < 4; j++) {
            int c0 = nb + 8 * j + 2 * t;
            float2 p0 = *(const float2*)&B0[(mb + g)     * PN + c0];
            float2 p1 = *(const float2*)&B0[(mb + g + 8) * PN + c0];
            *(float2*)&B0[(mb + g)     * PN + c0] =
                make_float2(1.5f * p0.x - 0.5f * a4[j][0], 1.5f * p0.y - 0.5f * a4[j][1]);
            *(float2*)&B0[(mb + g + 8) * PN + c0] =
                make_float2(1.5f * p1.x - 0.5f * a4[j][2], 1.5f * p1.y - 0.5f * a4[j][3]);
        }
        __syncthreads();
    }

    u64 acc[4][2], acc2[4][2];
    for (int it = 0; it < NS_FP; it++) {
        mm_sym(B0, B0, ib, jb, acc);
        mm_sym(B0, B1, ib, jb, acc2);
        store4(B2, ib, jb, acc);
        store4(B3, ib, jb, acc2);
        __syncthreads();
        mm_sym(B2, B3, ib, jb, acc);
#pragma unroll
        for (int ii = 0; ii < 4; ii++) {
            float2 l0 = unpk(acc[ii][0]);
            float2 l1 = unpk(acc[ii][1]);
            int base = (ib + ii) * PN + jb;
            float4 p = *(const float4*)&B0[base];
            *(float4*)&B0[base] = make_float4(1.5f * p.x - 0.5f * l0.x,
                                              1.5f * p.y - 0.5f * l0.y,
                                              1.5f * p.z - 0.5f * l1.x,
                                              1.5f * p.w - 0.5f * l1.y);
        }
        __syncthreads();
    }

#pragma unroll
    for (int ii = 0; ii < 4; ii++) {
        float4 p = *(const float4*)&B0[(ib + ii) * PN + jb];
        *(float4*)&d_wm[(ib + ii) * 64 + jb] =
            make_float4(p.x * srt, p.y * srt, p.z * srt, p.w * srt);
    }
    if (tid < 64) {
        float s = 0.f;
#pragma unroll 8
        for (int j = 0; j < 64; j++) s += B0[tid * PN + j] * (d_sums[j] * inv_m);
        d_off[tid] = beta[tid] - srt * s;
    }
}

// ---------------------------------------------------------------------------
// Kernel 3: out = x + E@x + off. 4 x-buffers + 2 y-buffers, ONE barrier/chunk
// (epoch e: output chunk e-1, prefetch chunk e+2, mma chunk e).
// ---------------------------------------------------------------------------
__global__ __launch_bounds__(256, 2) void apply_kernel(const float* __restrict__ X,
                                                       float* __restrict__ out) {
    __shared__ __align__(16) float xsh[4][64 * PA];   // 69.6 KB
    __shared__ __align__(16) float ysh[2][64 * PA];   // 34.8 KB
    __shared__ float osh[64];
    int tid = threadIdx.x, lane = tid & 31, w = tid >> 5;
    int g = lane >> 2, t = lane & 3;
    int mb = (w & 1) * 32, nb = (w >> 1) * 16;

    uint32_t sb[4];
#pragma unroll
    for (int i = 0; i < 4; i++)
        sb[i] = (uint32_t)__cvta_generic_to_shared(&xsh[i][0]);

    uint32_t ea[2][8][4];
#pragma unroll
    for (int mi = 0; mi < 2; mi++) {
        int r0 = mb + 16 * mi + g, r1 = r0 + 8;
#pragma unroll
        for (int ks = 0; ks < 8; ks++) {
            int c0 = 8 * ks + t, c1 = c0 + 4;
            ea[mi][ks][0] = tf32r(d_wm[r0 * 64 + c0] - (r0 == c0 ? 1.f : 0.f));
            ea[mi][ks][1] = tf32r(d_wm[r1 * 64 + c0] - (r1 == c0 ? 1.f : 0.f));
            ea[mi][ks][2] = tf32r(d_wm[r0 * 64 + c1] - (r0 == c1 ? 1.f : 0.f));
            ea[mi][ks][3] = tf32r(d_wm[r1 * 64 + c1] - (r1 == c1 ? 1.f : 0.f));
        }
    }
    if (tid < 64) osh[tid] = d_off[tid];

    // per-thread output slots (fixed across chunks)
    int oc[4], oq[4];
#pragma unroll
    for (int i = 0; i < 4; i++) {
        int f = tid + 256 * i;
        oc[i] = f >> 4; oq[i] = f & 15;
    }

    // preload chunks 0,1 into slots 0,1
#pragma unroll
    for (int p = 0; p < 2; p++) {
        int ch = blockIdx.x + p * GRIDB;
        int b = ch / CPI, pc = (ch - b * CPI) * 64;
        const float* base = X + b * CCH * HWP + pc;
#pragma unroll
        for (int i = 0; i < 4; i++) {
            cpa16(sb[p] + (oc[i] * PA + oq[i] * 4) * 4, base + oc[i] * HWP + oq[i] * 4);
        }
        cp_commit();
    }
    __syncthreads();          // osh visible
    float oo[4];
#pragma unroll
    for (int i = 0; i < 4; i++) oo[i] = osh[oc[i]];

    int it = 0;
    int prev_ch = 0;
    for (int ch = blockIdx.x; ch < NCHUNK; ch += GRIDB, it++) {
        cp_wait1();
        __syncthreads();

        // output chunk from previous epoch
        if (it > 0) {
            int b = prev_ch / CPI, pc = (prev_ch - b * CPI) * 64;
            float* ob = out + b * CCH * HWP + pc;
            const float* xp = &xsh[(it - 1) & 3][0];
            const float* yp = &ysh[(it - 1) & 1][0];
#pragma unroll
            for (int i = 0; i < 4; i++) {
                float4 xv = *(const float4*)&xp[oc[i] * PA + oq[i] * 4];
                float4 yv = *(const float4*)&yp[oc[i] * PA + oq[i] * 4];
                float o = oo[i];
                *(float4*)(ob + oc[i] * HWP + oq[i] * 4) =
                    make_float4(xv.x + yv.x + o, xv.y + yv.y + o,
                                xv.z + yv.z + o, xv.w + yv.w + o);
            }
        }

        // prefetch chunk+2 into slot (it+2)&3
        int cn = ch + 2 * GRIDB;
        if (cn < NCHUNK) {
            int b = cn / CPI, pc = (cn - b * CPI) * 64;
            const float* base = X + b * CCH * HWP + pc;
            uint32_t db = sb[(it + 2) & 3];
#pragma unroll
            for (int i = 0; i < 4; i++)
                cpa16(db + (oc[i] * PA + oq[i] * 4) * 4, base + oc[i] * HWP + oq[i] * 4);
            cp_commit();
        }

        // mma: E @ x for this chunk -> ysh[it&1]
        const float* xb = &xsh[it & 3][0];
        float* yw = &ysh[it & 1][0];
        float acc[2][2][4];
#pragma unroll
        for (int mi = 0; mi < 2; mi++)
#pragma unroll
            for (int j = 0; j < 2; j++)
#pragma unroll
                for (int e = 0; e < 4; e++) acc[mi][j][e] = 0.f;

#pragma unroll
        for (int ks = 0; ks < 8; ks++) {
            uint32_t b00 = fu(xb[(8 * ks + t)     * PA + nb + g]);
            uint32_t b01 = fu(xb[(8 * ks + t + 4) * PA + nb + g]);
            uint32_t b10 = fu(xb[(8 * ks + t)     * PA + nb + 8 + g]);
            uint32_t b11 = fu(xb[(8 * ks + t + 4) * PA + nb + 8 + g]);
#pragma unroll
            for (int mi = 0; mi < 2; mi++) {
                mma8(acc[mi][0], ea[mi][ks][0], ea[mi][ks][1],
                                 ea[mi][ks][2], ea[mi][ks][3], b00, b01);
                mma8(acc[mi][1], ea[mi][ks][0], ea[mi][ks][1],
                                 ea[mi][ks][2], ea[mi][ks][3], b10, b11);
            }
        }
#pragma unroll
        for (int mi = 0; mi < 2; mi++) {
            int r0 = mb + 16 * mi + g, r1 = r0 + 8;
#pragma unroll
            for (int j = 0; j < 2; j++) {
                int cc = nb + 8 * j + 2 * t;
                *(float2*)&yw[r0 * PA + cc] = make_float2(acc[mi][j][0], acc[mi][j][1]);
                *(float2*)&yw[r1 * PA + cc] = make_float2(acc[mi][j][2], acc[mi][j][3]);
            }
        }
        prev_ch = ch;
    }

    // drain: output the last chunk
    __syncthreads();
    if (it > 0) {
        int b = prev_ch / CPI, pc = (prev_ch - b * CPI) * 64;
        float* ob = out + b * CCH * HWP + pc;
        const float* xp = &xsh[(it - 1) & 3][0];
        const float* yp = &ysh[(it - 1) & 1][0];
#pragma unroll
        for (int i = 0; i < 4; i++) {
            float4 xv = *(const float4*)&xp[oc[i] * PA + oq[i] * 4];
            float4 yv = *(const float4*)&yp[oc[i] * PA + oq[i] * 4];
            float o = oo[i];
            *(float4*)(ob + oc[i] * HWP + oq[i] * 4) =
                make_float4(xv.x + yv.x + o, xv.y + yv.y + o,
                            xv.z + yv.z + o, xv.w + yv.w + o);
        }
    }
}

extern "C" void kernel_launch(void* const* d_in, const int* in_sizes, int n_in,
                              void* d_out, int out_size) {
    (void)in_sizes; (void)n_in; (void)out_size;
    const float* X    = (const float*)d_in[0];
    const float* beta = (const float*)d_in[1];
    float* out        = (float*)d_out;

    gram_kernel<<<GRIDB, 256>>>(X);
    reduce_kernel<<<33, 128>>>();
    ns_kernel<<<1, 256>>>(beta);
    apply_kernel<<<GRIDB, 256>>>(X, out);
}